// round 15
// baseline (speedup 1.0000x reference)
#include <cuda_runtime.h>
#include <cuda_bf16.h>
#include <cstdint>

#define FULL 0xffffffffu
#define EPS 1e-8f
#define WARPS 13
#define THREADS (WARPS * 32)
#define NUM_SMS 148
#define N_MAX 100000
#define M_MAX 50000

// Quantization: x,y -> 5 bits, z -> 6 bits over [-4.75, 4.75]
#define QOFF   4.75f
#define QSC_XY (31.0f / 9.5f)
#define QSC_Z  (63.0f / 9.5f)
#define QIV_XY (9.5f / 31.0f)
#define QIV_Z  (9.5f / 63.0f)
// half-steps: hxy=0.15323, hz=0.07540 ; ||h||=0.22945 ; (1+||h||)^2=1.5116
#define FILT_THRESH 1.5120f

__device__ float4 g_points4[N_MAX];
__device__ unsigned short g_quant[N_MAX + 8];
__device__ float4 g_q4[M_MAX];

__device__ __forceinline__ float fast_sqrt(float x) {
    float r;
    asm("sqrt.approx.ftz.f32 %0, %1;" : "=f"(r) : "f"(x));
    return r;
}

__device__ __forceinline__ void cp_async16(unsigned smem_addr, const void* gptr) {
    asm volatile("cp.async.cg.shared.global [%0], [%1], 16;\n"
                 :: "r"(smem_addr), "l"(gptr));
}
__device__ __forceinline__ void cp_commit() {
    asm volatile("cp.async.commit_group;\n" ::: "memory");
}
__device__ __forceinline__ void cp_wait1() {
    asm volatile("cp.async.wait_group 1;\n" ::: "memory");
}

__device__ __forceinline__ unsigned short quantize_pt(float x, float y, float z) {
    float fx = (x + QOFF) * QSC_XY;
    float fy = (y + QOFF) * QSC_XY;
    float fz = (z + QOFF) * QSC_Z;
    if (fx < 0.f || fx > 31.f || fy < 0.f || fy > 31.f || fz < 0.f || fz > 63.f)
        return 0xFFFFu;                       // out of range: force-pass sentinel
    int ix = __float2int_rn(fx);
    int iy = __float2int_rn(fy);
    int iz = __float2int_rn(fz);
    return (unsigned short)((ix << 11) | (iy << 6) | iz);
}

__global__ void pack_kernel(const float* __restrict__ points, int N,
                            const float* __restrict__ q_coords, int M) {
    int t = blockIdx.x * blockDim.x + threadIdx.x;
    int base = 4 * t;
    // points: vectorized 4-points-per-thread (3x LDG.128)
    if (base + 3 < N) {
        const float4* p4 = (const float4*)points;
        float4 a = p4[3 * t], b = p4[3 * t + 1], c = p4[3 * t + 2];
        g_points4[base + 0] = make_float4(a.x, a.y, a.z, 0.f);
        g_points4[base + 1] = make_float4(a.w, b.x, b.y, 0.f);
        g_points4[base + 2] = make_float4(b.z, b.w, c.x, 0.f);
        g_points4[base + 3] = make_float4(c.y, c.z, c.w, 0.f);
        g_quant[base + 0] = quantize_pt(a.x, a.y, a.z);
        g_quant[base + 1] = quantize_pt(a.w, b.x, b.y);
        g_quant[base + 2] = quantize_pt(b.z, b.w, c.x);
        g_quant[base + 3] = quantize_pt(c.y, c.z, c.w);
    } else if (base < N) {
        for (int i = base; i < N; i++) {
            float x = points[3 * i + 0];
            float y = points[3 * i + 1];
            float z = points[3 * i + 2];
            g_points4[i] = make_float4(x, y, z, 0.f);
            g_quant[i] = quantize_pt(x, y, z);
        }
    }
    // queries: same vectorized scheme
    if (base + 3 < M) {
        const float4* q4 = (const float4*)q_coords;
        float4 a = q4[3 * t], b = q4[3 * t + 1], c = q4[3 * t + 2];
        g_q4[base + 0] = make_float4(a.x, a.y, a.z, 0.f);
        g_q4[base + 1] = make_float4(a.w, b.x, b.y, 0.f);
        g_q4[base + 2] = make_float4(b.z, b.w, c.x, 0.f);
        g_q4[base + 3] = make_float4(c.y, c.z, c.w, 0.f);
    } else if (base < M) {
        for (int i = base; i < M; i++)
            g_q4[i] = make_float4(q_coords[3 * i + 0], q_coords[3 * i + 1],
                                  q_coords[3 * i + 2], 0.f);
    }
}

// Conservative prefilter on SMEM-resident quantized point (no false negatives).
__device__ __forceinline__ bool prefilter(unsigned short qv, float4 q) {
    if (qv == 0xFFFFu) return true;
    int ux = (qv >> 11) & 31;
    int uy = (qv >> 6) & 31;
    int uz = qv & 63;
    float dx = fmaf((float)ux, QIV_XY, -QOFF) - q.x;
    float dy = fmaf((float)uy, QIV_XY, -QOFF) - q.y;
    float dz = fmaf((float)uz, QIV_Z,  -QOFF) - q.z;
    float d2q = fmaf(dx, dx, fmaf(dy, dy, dz * dz));
    return d2q <= FILT_THRESH;
}

__global__ __launch_bounds__(THREADS, 1)
void gib_kernel(const int* __restrict__ support_idxs,
                const float* __restrict__ cy_radius,
                const float* __restrict__ disk_radius,
                const float* __restrict__ disk_width,
                const float* __restrict__ cone_radius,
                const float* __restrict__ cone_inc,
                const float* __restrict__ ellip_radii,
                const float* __restrict__ lambdas,
                float* __restrict__ out,
                int N, int M, int P /* query pairs */)
{
    extern __shared__ unsigned short s_quant[];       // N*2 bytes (~195 KB)
    __shared__ float4 s_coef[32];
    __shared__ float  s_inc[32];
    __shared__ float  s_lamT[16][36];                 // transposed, padded, /K folded
    __shared__ float4 s_stage[WARPS][2][64];          // 2-deep gather ring / surv alias

    int tid = threadIdx.x;

    if (tid < 32) {
        int kind = tid >> 3;
        int g    = tid & 7;
        float a = 0.f, b = 0.f, c = 0.f, e = 0.f, inc = 0.f;
        if (kind == 0) {                 // cylinder
            float r = cy_radius[g];
            float v = -0.5f / (r * r + EPS);
            a = v; b = v;
        } else if (kind == 1) {          // cone
            float r = cone_radius[g];
            e = -0.5f / (r * r + EPS);
            inc = cone_inc[g];
        } else if (kind == 2) {          // disk
            float r = disk_radius[g];
            float w = disk_width[g];
            float v = -0.5f / (r * r + EPS);
            a = v; b = v;
            c = -0.5f / (w * w + EPS);
        } else {                         // ellipsoid
            float ex = ellip_radii[g * 3 + 0];
            float ey = ellip_radii[g * 3 + 1];
            float ez = ellip_radii[g * 3 + 2];
            a = -0.5f / (ex * ex + EPS);
            b = -0.5f / (ey * ey + EPS);
            c = -0.5f / (ez * ez + EPS);
        }
        s_coef[tid] = make_float4(a, b, c, e);
        s_inc[tid] = inc;
    }
    for (int i = tid; i < 32 * 16; i += THREADS) {
        int j = i >> 4, o = i & 15;
        s_lamT[o][j] = lambdas[i] * (1.0f / 32.0f);   // fold masked-mean 1/K
    }

    // Load quant table into SMEM (coalesced uint4 stream from L2).
    {
        int nvec = (N + 7) / 8;                       // uint4 = 8 shorts
        const uint4* src = (const uint4*)g_quant;
        uint4* dst = (uint4*)s_quant;
        for (int i = tid; i < nvec; i += THREADS)
            dst[i] = src[i];
    }
    __syncthreads();

    int lane = tid & 31;
    int wid  = tid >> 5;
    unsigned ltmask = (1u << lane) - 1u;

    float4 cf  = s_coef[lane];
    float  inc = s_inc[lane];

    int gw     = blockIdx.x * WARPS + wid;
    int stride = gridDim.x * WARPS;

    int p = gw;
    if (p >= P) return;

    unsigned stage0 = (unsigned)__cvta_generic_to_shared(&s_stage[wid][0][0]);
    unsigned stage1 = (unsigned)__cvta_generic_to_shared(&s_stage[wid][1][0]);

    // ---- Prologue: prefilter pair p + issue its (predicated) gathers ----
    float4 qc0, qc1;
    bool passA, passB;
    {
        int m0 = 2 * p;
        int m1 = min(2 * p + 1, M - 1);
        int ia = __ldcg(&support_idxs[m0 * 32 + lane]);
        int ib = __ldcg(&support_idxs[m1 * 32 + lane]);
        qc0 = __ldg(&g_q4[m0]);
        qc1 = __ldg(&g_q4[m1]);
        passA = prefilter(s_quant[ia], qc0);
        passB = prefilter(s_quant[ib], qc1);
        if (passA) cp_async16(stage0 + lane * 16,        &g_points4[ia]);
        if (passB) cp_async16(stage0 + (32 + lane) * 16, &g_points4[ib]);
    }
    cp_commit();

    // idx prefetch for pair p+stride
    int pn = p + stride;
    int ian = 0, ibn = 0;
    if (pn < P) {
        ian = __ldcg(&support_idxs[(2 * pn) * 32 + lane]);
        ibn = __ldcg(&support_idxs[min(2 * pn + 1, M - 1) * 32 + lane]);
    }

    int buf = 0;
    while (p < P) {
        // ---- Stage pair pn: prefilter + predicated cp.async into other buf ----
        float4 qc0n = qc0, qc1n = qc1;
        bool passAn = false, passBn = false;
        if (pn < P) {
            int mn0 = 2 * pn;
            int mn1 = min(2 * pn + 1, M - 1);
            qc0n = __ldg(&g_q4[mn0]);
            qc1n = __ldg(&g_q4[mn1]);
            passAn = prefilter(s_quant[ian], qc0n);
            passBn = prefilter(s_quant[ibn], qc1n);
            unsigned tnext = buf ? stage0 : stage1;
            if (passAn) cp_async16(tnext + lane * 16,        &g_points4[ian]);
            if (passBn) cp_async16(tnext + (32 + lane) * 16, &g_points4[ibn]);
        }
        cp_commit();

        int pnn = pn + stride;
        if (pnn < P) {
            ian = __ldcg(&support_idxs[(2 * pnn) * 32 + lane]);
            ibn = __ldcg(&support_idxs[min(2 * pnn + 1, M - 1) * 32 + lane]);
        }

        // ---- Current pair's gathers complete (1 group still in flight) ----
        cp_wait1();

        int m0 = 2 * p;
        float4* curt = &s_stage[wid][buf][0];
        float x2a = 0.f, y2a = 0.f, za = 0.f, rxya = 0.f, d2a = 9e9f;
        float x2b = 0.f, y2b = 0.f, zb = 0.f, rxyb = 0.f, d2b = 9e9f;
        if (passA) {
            float4 pt = curt[lane];
            float x = pt.x - qc0.x, y = pt.y - qc0.y;
            za = pt.z - qc0.z;
            x2a = x * x; y2a = y * y;
            float xy2 = x2a + y2a;
            d2a = xy2 + za * za;
            rxya = fast_sqrt(xy2 + EPS);
        }
        if (passB) {
            float4 pt = curt[32 + lane];
            float x = pt.x - qc1.x, y = pt.y - qc1.y;
            zb = pt.z - qc1.z;
            x2b = x * x; y2b = y * y;
            float xy2 = x2b + y2b;
            d2b = xy2 + zb * zb;
            rxyb = fast_sqrt(xy2 + EPS);
        }

        bool alive0 = (d2a <= 1.0f);
        bool alive1 = (d2b <= 1.0f) && (2 * p + 1 < M);
        // Ballots = warp convergence: all lanes' curt reads done -> alias safe.
        unsigned b0 = __ballot_sync(FULL, alive0);
        unsigned b1 = __ballot_sync(FULL, alive1);
        int n0 = __popc(b0);
        int n1 = __popc(b1);

        float4* surv = curt;               // alias: [0..31]=q0, [32..63]=q1
        if (alive0) surv[__popc(b0 & ltmask)]      = make_float4(x2a, y2a, za, rxya);
        if (alive1) surv[32 + __popc(b1 & ltmask)] = make_float4(x2b, y2b, zb, rxyb);
        __syncwarp();

        float acc0 = 0.0f, acc1 = 0.0f;
        int nmax = max(n0, n1);
        #pragma unroll 2
        for (int j = 0; j < nmax; j++) {
            if (j < n0) {
                float4 v = surv[j];
                float dd = fmaf(-inc, v.z, v.w);
                float t = fmaf(cf.x, v.x,
                          fmaf(cf.y, v.y,
                          fmaf(cf.z, v.z * v.z, (cf.w * dd) * dd)));
                acc0 += __expf(t);
            }
            if (j < n1) {
                float4 v = surv[32 + j];
                float dd = fmaf(-inc, v.z, v.w);
                float t = fmaf(cf.x, v.x,
                          fmaf(cf.y, v.y,
                          fmaf(cf.z, v.z * v.z, (cf.w * dd) * dd)));
                acc1 += __expf(t);
            }
        }
        __syncwarp();

        // Stage accumulators (alias again — survivor data now dead).
        float* accp = (float*)surv;
        accp[lane]      = acc0;
        accp[32 + lane] = acc1;
        __syncwarp();

        // Epilogue: lanes 0-15 -> q0, lanes 16-31 -> q1.
        int qsel = lane >> 4;
        int o    = lane & 15;
        int mst  = qsel ? (2 * p + 1) : m0;
        if (mst < M) {
            const float* arow = accp + qsel * 32;
            float ot = 0.0f;
            #pragma unroll
            for (int j = 0; j < 32; j += 4) {
                float4 lam4 = *(const float4*)&s_lamT[o][j];
                float4 a4   = *(const float4*)&arow[j];
                ot = fmaf(a4.x, lam4.x,
                     fmaf(a4.y, lam4.y,
                     fmaf(a4.z, lam4.z,
                     fmaf(a4.w, lam4.w, ot))));
            }
            out[mst * 16 + o] = ot;
        }
        __syncwarp();   // epilogue reads complete before next cp.async into curt

        // ---- Rotate pipeline ----
        p = pn; pn = pnn;
        qc0 = qc0n; qc1 = qc1n;
        passA = passAn; passB = passBn;
        buf ^= 1;
    }
}

extern "C" void kernel_launch(void* const* d_in, const int* in_sizes, int n_in,
                              void* d_out, int out_size) {
    const float* points       = (const float*)d_in[0];
    const float* q_coords     = (const float*)d_in[1];
    const int*   support_idxs = (const int*)  d_in[2];
    const float* cy_radius    = (const float*)d_in[3];
    const float* disk_radius  = (const float*)d_in[4];
    const float* disk_width   = (const float*)d_in[5];
    const float* cone_radius  = (const float*)d_in[6];
    const float* cone_inc     = (const float*)d_in[7];
    const float* ellip_radii  = (const float*)d_in[8];
    const float* lambdas      = (const float*)d_in[9];
    float* out = (float*)d_out;

    int N = in_sizes[0] / 3;   // points has N*3 elements
    int M = in_sizes[1] / 3;   // q_coords has M*3 elements
    int P = (M + 1) / 2;       // query pairs

    int packWork = ((N > M ? N : M) + 3) / 4;
    pack_kernel<<<(packWork + 255) / 256, 256>>>(points, N, q_coords, M);

    // Dynamic smem for the quant table (uint4 granularity).
    int smemBytes = ((N + 7) / 8) * 16;
    cudaFuncSetAttribute(gib_kernel,
                         cudaFuncAttributeMaxDynamicSharedMemorySize, smemBytes);

    int needBlocks = (P + WARPS - 1) / WARPS;
    int blocks = needBlocks < NUM_SMS ? needBlocks : NUM_SMS;
    gib_kernel<<<blocks, THREADS, smemBytes>>>(support_idxs,
                                    cy_radius, disk_radius, disk_width,
                                    cone_radius, cone_inc, ellip_radii,
                                    lambdas, out, N, M, P);
}

// round 16
// speedup vs baseline: 1.4111x; 1.4111x over previous
#include <cuda_runtime.h>
#include <cuda_bf16.h>
#include <cstdint>

#define FULL 0xffffffffu
#define EPS 1e-8f
#define WARPS_PER_BLOCK 8
#define THREADS (WARPS_PER_BLOCK * 32)
#define BLOCKS_PER_SM 8
#define NUM_SMS 148
#define N_MAX 100000
#define M_MAX 50000

// Packed scratch (filled by prepass): points and queries as float4.
__device__ float4 g_points4[N_MAX];
__device__ float4 g_q4[M_MAX];

__device__ __forceinline__ float fast_sqrt(float x) {
    float r;
    asm("sqrt.approx.ftz.f32 %0, %1;" : "=f"(r) : "f"(x));
    return r;
}

__device__ __forceinline__ void cp_async16(unsigned smem_addr, const void* gptr) {
    asm volatile("cp.async.cg.shared.global [%0], [%1], 16;\n"
                 :: "r"(smem_addr), "l"(gptr));
}
__device__ __forceinline__ void cp_commit() {
    asm volatile("cp.async.commit_group;\n" ::: "memory");
}
__device__ __forceinline__ void cp_wait1() {
    asm volatile("cp.async.wait_group 1;\n" ::: "memory");
}

// Vectorized pack: 4 points per thread via 3x LDG.128, coalesced float4 stores.
__global__ void pack_kernel(const float* __restrict__ points, int N,
                            const float* __restrict__ q_coords, int M) {
    int t = blockIdx.x * blockDim.x + threadIdx.x;
    int base = 4 * t;
    if (base + 3 < N) {
        const float4* p4 = (const float4*)points;
        float4 a = p4[3 * t], b = p4[3 * t + 1], c = p4[3 * t + 2];
        g_points4[base + 0] = make_float4(a.x, a.y, a.z, 0.f);
        g_points4[base + 1] = make_float4(a.w, b.x, b.y, 0.f);
        g_points4[base + 2] = make_float4(b.z, b.w, c.x, 0.f);
        g_points4[base + 3] = make_float4(c.y, c.z, c.w, 0.f);
    } else if (base < N) {
        for (int i = base; i < N; i++)
            g_points4[i] = make_float4(points[3 * i + 0], points[3 * i + 1],
                                       points[3 * i + 2], 0.f);
    }
    if (base + 3 < M) {
        const float4* q4 = (const float4*)q_coords;
        float4 a = q4[3 * t], b = q4[3 * t + 1], c = q4[3 * t + 2];
        g_q4[base + 0] = make_float4(a.x, a.y, a.z, 0.f);
        g_q4[base + 1] = make_float4(a.w, b.x, b.y, 0.f);
        g_q4[base + 2] = make_float4(b.z, b.w, c.x, 0.f);
        g_q4[base + 3] = make_float4(c.y, c.z, c.w, 0.f);
    } else if (base < M) {
        for (int i = base; i < M; i++)
            g_q4[i] = make_float4(q_coords[3 * i + 0], q_coords[3 * i + 1],
                                  q_coords[3 * i + 2], 0.f);
    }
}

__global__ __launch_bounds__(THREADS, BLOCKS_PER_SM)
void gib_kernel(const int* __restrict__ support_idxs,
                const float* __restrict__ cy_radius,
                const float* __restrict__ disk_radius,
                const float* __restrict__ disk_width,
                const float* __restrict__ cone_radius,
                const float* __restrict__ cone_inc,
                const float* __restrict__ ellip_radii,
                const float* __restrict__ lambdas,
                float* __restrict__ out,
                int M, int P /* number of query pairs */)
{
    __shared__ float4 s_coef[32];
    __shared__ float  s_inc[32];
    __shared__ float  s_lamT[16][36];                  // transposed, padded, /K folded
    __shared__ float4 s_tile[WARPS_PER_BLOCK][2][64];  // double-buffered gathered pts
    // Survivor compaction + acc staging ALIAS s_tile[wid][buf] — that buffer's
    // point data is dead once pa/pb are in registers, and the next cp.async
    // into it is only issued after the epilogue __syncwarp.

    int tid = threadIdx.x;

    if (tid < 32) {
        int kind = tid >> 3;
        int g    = tid & 7;
        float a = 0.f, b = 0.f, c = 0.f, e = 0.f, inc = 0.f;
        if (kind == 0) {                 // cylinder
            float r = cy_radius[g];
            float v = -0.5f / (r * r + EPS);
            a = v; b = v;
        } else if (kind == 1) {          // cone
            float r = cone_radius[g];
            e = -0.5f / (r * r + EPS);
            inc = cone_inc[g];
        } else if (kind == 2) {          // disk
            float r = disk_radius[g];
            float w = disk_width[g];
            float v = -0.5f / (r * r + EPS);
            a = v; b = v;
            c = -0.5f / (w * w + EPS);
        } else {                         // ellipsoid
            float ex = ellip_radii[g * 3 + 0];
            float ey = ellip_radii[g * 3 + 1];
            float ez = ellip_radii[g * 3 + 2];
            a = -0.5f / (ex * ex + EPS);
            b = -0.5f / (ey * ey + EPS);
            c = -0.5f / (ez * ez + EPS);
        }
        s_coef[tid] = make_float4(a, b, c, e);
        s_inc[tid] = inc;
    }
    for (int i = tid; i < 32 * 16; i += THREADS) {
        int j = i >> 4, o = i & 15;
        s_lamT[o][j] = lambdas[i] * (1.0f / 32.0f);    // fold masked-mean 1/K
    }
    __syncthreads();

    int lane = tid & 31;
    int wid  = tid >> 5;
    unsigned ltmask = (1u << lane) - 1u;

    float4 cf  = s_coef[lane];
    float  inc = s_inc[lane];

    int gw     = blockIdx.x * WARPS_PER_BLOCK + wid;
    int stride = gridDim.x * WARPS_PER_BLOCK;

    int p = gw;
    if (p >= P) return;

    unsigned tile0 = (unsigned)__cvta_generic_to_shared(&s_tile[wid][0][0]);
    unsigned tile1 = (unsigned)__cvta_generic_to_shared(&s_tile[wid][1][0]);

    // ---- Prologue: stage pair p into buf0 ----
    {
        int m0 = 2 * p;
        int m1 = min(2 * p + 1, M - 1);
        int ia = __ldg(&support_idxs[m0 * 32 + lane]);
        int ib = __ldg(&support_idxs[m1 * 32 + lane]);
        cp_async16(tile0 + lane * 16,        &g_points4[ia]);
        cp_async16(tile0 + (32 + lane) * 16, &g_points4[ib]);
    }
    cp_commit();

    // idx for pair p+stride
    int pn = p + stride;
    int ian = 0, ibn = 0;
    if (pn < P) {
        ian = __ldg(&support_idxs[(2 * pn) * 32 + lane]);
        ibn = __ldg(&support_idxs[min(2 * pn + 1, M - 1) * 32 + lane]);
    }

    int buf = 0;
    while (p < P) {
        // ---- Stage next pair into other buffer ----
        unsigned tnext = buf ? tile0 : tile1;
        if (pn < P) {
            cp_async16(tnext + lane * 16,        &g_points4[ian]);
            cp_async16(tnext + (32 + lane) * 16, &g_points4[ibn]);
        }
        cp_commit();

        int pnn = pn + stride;
        if (pnn < P) {
            ian = __ldg(&support_idxs[(2 * pnn) * 32 + lane]);
            ibn = __ldg(&support_idxs[min(2 * pnn + 1, M - 1) * 32 + lane]);
        }

        // ---- Current pair ready after wait (1 group still in flight).
        // Each lane reads only SMEM its own cp.asyncs wrote -> no syncwarp.
        cp_wait1();

        int m0 = 2 * p;
        int m1 = min(2 * p + 1, M - 1);
        float4* curt = &s_tile[wid][buf][0];
        float4 pa = curt[lane];
        float4 pb = curt[32 + lane];
        float4 qa = g_q4[m0];          // broadcast, L1-resident
        float4 qb = g_q4[m1];

        float xa = pa.x - qa.x, ya = pa.y - qa.y, za = pa.z - qa.z;
        float xb = pb.x - qb.x, yb = pb.y - qb.y, zb = pb.z - qb.z;
        float x2a = xa * xa, y2a = ya * ya;
        float x2b = xb * xb, y2b = yb * yb;
        float xy2a = x2a + y2a, xy2b = x2b + y2b;
        float d2a = xy2a + za * za;
        float d2b = xy2b + zb * zb;
        float rxya = fast_sqrt(xy2a + EPS);
        float rxyb = fast_sqrt(xy2b + EPS);

        bool alive0 = (d2a <= 1.0f);
        bool alive1 = (d2b <= 1.0f) && (m1 == 2 * p + 1);
        // Ballots are warp-collective: every lane has consumed pa/pb before
        // any lane proceeds -> safe to overwrite curt (alias) below.
        unsigned b0 = __ballot_sync(FULL, alive0);
        unsigned b1 = __ballot_sync(FULL, alive1);
        int n0 = __popc(b0);
        int n1 = __popc(b1);

        float4* surv = curt;           // alias: slots [0..31]=q0, [32..63]=q1
        if (alive0) surv[__popc(b0 & ltmask)]      = make_float4(x2a, y2a, za, rxya);
        if (alive1) surv[32 + __popc(b1 & ltmask)] = make_float4(x2b, y2b, zb, rxyb);
        __syncwarp();

        float acc0 = 0.0f, acc1 = 0.0f;
        int nmax = max(n0, n1);
        #pragma unroll 2
        for (int j = 0; j < nmax; j++) {
            if (j < n0) {
                float4 v = surv[j];
                float dd = fmaf(-inc, v.z, v.w);
                float t = fmaf(cf.x, v.x,
                          fmaf(cf.y, v.y,
                          fmaf(cf.z, v.z * v.z, (cf.w * dd) * dd)));
                acc0 += __expf(t);
            }
            if (j < n1) {
                float4 v = surv[32 + j];
                float dd = fmaf(-inc, v.z, v.w);
                float t = fmaf(cf.x, v.x,
                          fmaf(cf.y, v.y,
                          fmaf(cf.z, v.z * v.z, (cf.w * dd) * dd)));
                acc1 += __expf(t);
            }
        }
        __syncwarp();

        // Stage accumulators (alias again — survivor data now dead).
        float* accp = (float*)surv;
        accp[lane]      = acc0;
        accp[32 + lane] = acc1;
        __syncwarp();

        int qsel = lane >> 4;
        int o    = lane & 15;
        int mst  = qsel ? (2 * p + 1) : m0;
        if (mst < M) {
            const float* arow = accp + qsel * 32;
            float ot = 0.0f;
            #pragma unroll
            for (int j = 0; j < 32; j += 4) {
                float4 lam4 = *(const float4*)&s_lamT[o][j];
                float4 a4   = *(const float4*)&arow[j];
                ot = fmaf(a4.x, lam4.x,
                     fmaf(a4.y, lam4.y,
                     fmaf(a4.z, lam4.z,
                     fmaf(a4.w, lam4.w, ot))));
            }
            out[mst * 16 + o] = ot;
        }
        __syncwarp();   // epilogue reads done before next cp.async into curt

        // ---- Rotate ----
        p = pn; pn = pnn;
        buf ^= 1;
    }
}

extern "C" void kernel_launch(void* const* d_in, const int* in_sizes, int n_in,
                              void* d_out, int out_size) {
    const float* points       = (const float*)d_in[0];
    const float* q_coords     = (const float*)d_in[1];
    const int*   support_idxs = (const int*)  d_in[2];
    const float* cy_radius    = (const float*)d_in[3];
    const float* disk_radius  = (const float*)d_in[4];
    const float* disk_width   = (const float*)d_in[5];
    const float* cone_radius  = (const float*)d_in[6];
    const float* cone_inc     = (const float*)d_in[7];
    const float* ellip_radii  = (const float*)d_in[8];
    const float* lambdas      = (const float*)d_in[9];
    float* out = (float*)d_out;

    int N = in_sizes[0] / 3;   // points has N*3 elements
    int M = in_sizes[1] / 3;   // q_coords has M*3 elements
    int P = (M + 1) / 2;       // query pairs

    int packWork = ((N > M ? N : M) + 3) / 4;
    pack_kernel<<<(packWork + 255) / 256, 256>>>(points, N, q_coords, M);

    int maxBlocks = NUM_SMS * BLOCKS_PER_SM;
    int needBlocks = (P + WARPS_PER_BLOCK - 1) / WARPS_PER_BLOCK;
    int blocks = needBlocks < maxBlocks ? needBlocks : maxBlocks;
    gib_kernel<<<blocks, THREADS>>>(support_idxs,
                                    cy_radius, disk_radius, disk_width,
                                    cone_radius, cone_inc, ellip_radii,
                                    lambdas, out, M, P);
}